// round 9
// baseline (speedup 1.0000x reference)
#include <cuda_runtime.h>
#include <cuda_bf16.h>
#include <cstdint>
#include <cstddef>

// Problem dims (fixed by the dataset)
#define BATCH   8192
#define NREG    14
#define DDIM    768
#define M_TOTAL (BATCH * NREG)   // 114688 = 128 * 896
#define K_DIM   768              // 32 * 24
#define N_DIM   768              // 128 * 6

// ---------------------------------------------------------------------------
// Device scratch (allocation-free rule: __device__ globals)
// ---------------------------------------------------------------------------
__device__ __nv_bfloat16 g_Abf[(size_t)M_TOTAL * K_DIM];   // X in bf16
__device__ __nv_bfloat16 g_Wbf[(size_t)K_DIM * N_DIM];     // W in bf16
__device__ __nv_bfloat16 g_feats[(size_t)M_TOTAL * N_DIM]; // X@W + b in bf16

// ---------------------------------------------------------------------------
// fp32 -> bf16 converters (8 elems / thread, fully vectorized)
// ---------------------------------------------------------------------------
__global__ __launch_bounds__(256) void cvtA_kernel(const float* __restrict__ src) {
    size_t i = ((size_t)blockIdx.x * 256 + threadIdx.x) * 8;
    float4 v0 = *(const float4*)(src + i);
    float4 v1 = *(const float4*)(src + i + 4);
    union { __nv_bfloat162 h[4]; uint4 u; } pk;
    pk.h[0] = __floats2bfloat162_rn(v0.x, v0.y);
    pk.h[1] = __floats2bfloat162_rn(v0.z, v0.w);
    pk.h[2] = __floats2bfloat162_rn(v1.x, v1.y);
    pk.h[3] = __floats2bfloat162_rn(v1.z, v1.w);
    *(uint4*)(g_Abf + i) = pk.u;
}

__global__ __launch_bounds__(256) void cvtW_kernel(const float* __restrict__ src) {
    size_t i = ((size_t)blockIdx.x * 256 + threadIdx.x) * 8;
    float4 v0 = *(const float4*)(src + i);
    float4 v1 = *(const float4*)(src + i + 4);
    union { __nv_bfloat162 h[4]; uint4 u; } pk;
    pk.h[0] = __floats2bfloat162_rn(v0.x, v0.y);
    pk.h[1] = __floats2bfloat162_rn(v0.z, v0.w);
    pk.h[2] = __floats2bfloat162_rn(v1.x, v1.y);
    pk.h[3] = __floats2bfloat162_rn(v1.z, v1.w);
    *(uint4*)(g_Wbf + i) = pk.u;
}

// ---------------------------------------------------------------------------
// bf16 tensor-core GEMM: feats[M,768] = Abf[M,768] @ Wbf[768,768] + bias
// BM=128, BN=128, BK=32, 256 threads (8 warps, warp tile 32x64), 3-stage
// cp.async pipeline (48 KB static smem = ptxas limit), xor-swizzled smem.
// ---------------------------------------------------------------------------
__device__ __forceinline__ void cp_async16(uint32_t smem, const void* g) {
    asm volatile("cp.async.cg.shared.global [%0], [%1], 16;\n" :: "r"(smem), "l"(g));
}
__device__ __forceinline__ void ldm_x4(uint32_t& r0, uint32_t& r1, uint32_t& r2, uint32_t& r3,
                                       uint32_t addr) {
    asm volatile("ldmatrix.sync.aligned.m8n8.x4.shared.b16 {%0,%1,%2,%3}, [%4];"
                 : "=r"(r0), "=r"(r1), "=r"(r2), "=r"(r3) : "r"(addr));
}
__device__ __forceinline__ void ldm_x4_t(uint32_t& r0, uint32_t& r1, uint32_t& r2, uint32_t& r3,
                                         uint32_t addr) {
    asm volatile("ldmatrix.sync.aligned.m8n8.x4.trans.shared.b16 {%0,%1,%2,%3}, [%4];"
                 : "=r"(r0), "=r"(r1), "=r"(r2), "=r"(r3) : "r"(addr));
}
__device__ __forceinline__ void mma_bf16(float* d, const uint32_t* a, uint32_t b0, uint32_t b1) {
    asm volatile("mma.sync.aligned.m16n8k16.row.col.f32.bf16.bf16.f32 "
                 "{%0,%1,%2,%3}, {%4,%5,%6,%7}, {%8,%9}, {%0,%1,%2,%3};"
                 : "+f"(d[0]), "+f"(d[1]), "+f"(d[2]), "+f"(d[3])
                 : "r"(a[0]), "r"(a[1]), "r"(a[2]), "r"(a[3]), "r"(b0), "r"(b1));
}

#define KTILES 24
#define STAGES 3

__global__ __launch_bounds__(256, 2) void gemm_kernel(const float* __restrict__ bias) {
    __shared__ __nv_bfloat16 sA[STAGES][128 * 32];   // 24 KB
    __shared__ __nv_bfloat16 sB[STAGES][32 * 128];   // 24 KB  (total 48 KB = static max)

    const int tid  = threadIdx.x;
    const int lane = tid & 31;
    const int wid  = tid >> 5;
    const int wm   = (wid & 3) * 32;   // warp row offset within 128
    const int wn   = (wid >> 2) * 64;  // warp col offset within 128
    const int bn0  = blockIdx.x * 128;
    const size_t Abase = (size_t)blockIdx.y * 128 * K_DIM;

    const uint32_t sA_u = (uint32_t)__cvta_generic_to_shared(&sA[0][0]);
    const uint32_t sB_u = (uint32_t)__cvta_generic_to_shared(&sB[0][0]);

    auto loadTiles = [&](int stage, int kt) {
        // A tile: 128 rows x 4 chunks(16B). swizzle: chunk ^= (row>>1)&3
        #pragma unroll
        for (int j = 0; j < 2; j++) {
            int id = tid + j * 256;
            int r  = id >> 2, c = id & 3;
            const __nv_bfloat16* src = g_Abf + Abase + (size_t)r * K_DIM + kt * 32 + c * 8;
            int swc = c ^ ((r >> 1) & 3);
            cp_async16(sA_u + (uint32_t)((stage * 4096 + r * 32 + swc * 8) * 2), src);
        }
        // B tile: 32 rows x 16 chunks(16B). swizzle: chunk ^= row&7
        #pragma unroll
        for (int j = 0; j < 2; j++) {
            int id = tid + j * 256;
            int k  = id >> 4, c = id & 15;
            const __nv_bfloat16* src = g_Wbf + (size_t)(kt * 32 + k) * N_DIM + bn0 + c * 8;
            int swc = c ^ (k & 7);
            cp_async16(sB_u + (uint32_t)((stage * 4096 + k * 128 + swc * 8) * 2), src);
        }
        asm volatile("cp.async.commit_group;\n");
    };

    float acc[2][8][4];
    #pragma unroll
    for (int mf = 0; mf < 2; mf++)
        #pragma unroll
        for (int nf = 0; nf < 8; nf++)
            #pragma unroll
            for (int i = 0; i < 4; i++) acc[mf][nf][i] = 0.f;

    loadTiles(0, 0);
    loadTiles(1, 1);

    int cur = 0, nxt = 2;
    for (int kt = 0; kt < KTILES; kt++) {
        if (kt < KTILES - 1) asm volatile("cp.async.wait_group 1;\n");
        else                 asm volatile("cp.async.wait_group 0;\n");
        __syncthreads();
        if (kt + 2 < KTILES) loadTiles(nxt, kt + 2);

        #pragma unroll
        for (int kk = 0; kk < 2; kk++) {
            uint32_t afr[2][4], bfr[16];
            #pragma unroll
            for (int mf = 0; mf < 2; mf++) {
                int r   = wm + mf * 16 + (lane & 15);
                int ch  = kk * 2 + (lane >> 4);
                int swc = ch ^ ((r >> 1) & 3);
                ldm_x4(afr[mf][0], afr[mf][1], afr[mf][2], afr[mf][3],
                       sA_u + (uint32_t)((cur * 4096 + r * 32 + swc * 8) * 2));
            }
            #pragma unroll
            for (int nq = 0; nq < 4; nq++) {
                int k   = kk * 16 + (lane & 15);
                int ch  = (wn >> 3) + nq * 2 + (lane >> 4);
                int swc = ch ^ (k & 7);
                ldm_x4_t(bfr[nq * 4 + 0], bfr[nq * 4 + 1], bfr[nq * 4 + 2], bfr[nq * 4 + 3],
                         sB_u + (uint32_t)((cur * 4096 + k * 128 + swc * 8) * 2));
            }
            #pragma unroll
            for (int mf = 0; mf < 2; mf++)
                #pragma unroll
                for (int nf = 0; nf < 8; nf++)
                    mma_bf16(acc[mf][nf], afr[mf], bfr[2 * nf], bfr[2 * nf + 1]);
        }
        cur = cur == 2 ? 0 : cur + 1;
        nxt = nxt == 2 ? 0 : nxt + 1;
    }

    // Epilogue: add bias (L1/L2-cached float2 loads), convert to bf16, store feats
    const int g = lane >> 2, t4 = lane & 3;
    #pragma unroll
    for (int mf = 0; mf < 2; mf++) {
        size_t row0 = (size_t)blockIdx.y * 128 + wm + mf * 16 + g;
        #pragma unroll
        for (int nf = 0; nf < 8; nf++) {
            int col   = wn + nf * 8 + t4 * 2;
            float2 bb = __ldg((const float2*)(bias + bn0 + col));
            __nv_bfloat162 v0 = __floats2bfloat162_rn(acc[mf][nf][0] + bb.x, acc[mf][nf][1] + bb.y);
            __nv_bfloat162 v1 = __floats2bfloat162_rn(acc[mf][nf][2] + bb.x, acc[mf][nf][3] + bb.y);
            *(__nv_bfloat162*)(g_feats + row0 * N_DIM + bn0 + col)       = v0;
            *(__nv_bfloat162*)(g_feats + (row0 + 8) * N_DIM + bn0 + col) = v1;
        }
    }
}

// ---------------------------------------------------------------------------
// Per-batch kernel: Gram (14x14) via warp-per-row over bf16 smem (halves the
// smem crossbar traffic vs fp32 staging), norms, weighting, softmax.
// One block per batch, 448 threads = 14 warps.
// ---------------------------------------------------------------------------
#define FS_PITCH 776   // bf16 elements per row (768 + 8 pad)

__global__ __launch_bounds__(448, 2) void batch_kernel(const float* __restrict__ area,
                                                       const float* __restrict__ co,
                                                       float* __restrict__ out) {
    __shared__ __nv_bfloat16 Fs[NREG * FS_PITCH];  // 21.2 KB, raw bf16 feats
    __shared__ float G[14][16];      // padded
    __shared__ float s_area[14];
    __shared__ float s_rnorm[14];
    __shared__ float s_scal[2];      // [0] = 1/(cwsum+eps), [1] = 1/(amax^2+eps)

    const int b = blockIdx.x, tid = threadIdx.x;
    const int wid = tid >> 5, lane = tid & 31;

    // Stage feats: raw bf16 copy, 16B per thread per iter (3 iters exactly)
    const uint4* fb = (const uint4*)(g_feats + (size_t)b * NREG * DDIM);
    for (int idx = tid; idx < NREG * 96; idx += 448) {
        int n = idx / 96, c = idx - n * 96;            // c in 16B units (8 bf16)
        *(uint4*)(Fs + n * FS_PITCH + c * 8) = fb[idx];
    }
    if (tid < NREG) s_area[tid] = area[b * NREG + tid];
    if (tid == 14) {  // deterministic cw sum (exact fp32 serial)
        float s = 0.f;
        for (int i = 0; i < NREG * NREG; i++) s += co[i];
        s_scal[0] = 1.0f / (s + 1e-8f);
    }
    if (tid == 15) {  // max(aw) == (max a)^2 since a >= 0
        float am = 0.f;
        for (int i = 0; i < NREG; i++) am = fmaxf(am, area[b * NREG + i]);
        s_scal[1] = 1.0f / (am * am + 1e-8f);
    }
    __syncthreads();

    // Gram: warp `wid` computes row wid. Own row cached unpacked in fp32 regs;
    // partner rows read as bf16 uint2 (8B/lane, contiguous 256B/warp -> no conflicts).
    {
        float creg[24];
        const __nv_bfloat16* rowp = Fs + wid * FS_PITCH;
        #pragma unroll
        for (int j = 0; j < 6; j++) {
            uint2 raw = *(const uint2*)(rowp + j * 128 + lane * 4);
            float2 lo = __bfloat1622float2(*(const __nv_bfloat162*)&raw.x);
            float2 hi = __bfloat1622float2(*(const __nv_bfloat162*)&raw.y);
            creg[4 * j + 0] = lo.x; creg[4 * j + 1] = lo.y;
            creg[4 * j + 2] = hi.x; creg[4 * j + 3] = hi.y;
        }
        #pragma unroll 2
        for (int m = 0; m < NREG; m++) {
            const __nv_bfloat16* mp = Fs + m * FS_PITCH;
            float acc = 0.f;
            #pragma unroll
            for (int j = 0; j < 6; j++) {
                uint2 raw = *(const uint2*)(mp + j * 128 + lane * 4);
                float2 lo = __bfloat1622float2(*(const __nv_bfloat162*)&raw.x);
                float2 hi = __bfloat1622float2(*(const __nv_bfloat162*)&raw.y);
                acc += creg[4 * j + 0] * lo.x + creg[4 * j + 1] * lo.y
                     + creg[4 * j + 2] * hi.x + creg[4 * j + 3] * hi.y;
            }
            #pragma unroll
            for (int off = 16; off > 0; off >>= 1)
                acc += __shfl_xor_sync(0xFFFFFFFFu, acc, off);
            if (lane == 0) G[wid][m] = acc;
        }
    }
    __syncthreads();

    if (tid < NREG) {
        float nn = sqrtf(G[tid][tid]);
        s_rnorm[tid] = 1.0f / fmaxf(nn, 1e-12f);
    }
    __syncthreads();

    if (tid < NREG) {
        const int n = tid;
        float vals[NREG];
        const float an = s_area[n], rn = s_rnorm[n];
        const float inv_cw = s_scal[0], inv_aw = s_scal[1];
        float mx = -1e30f;
        #pragma unroll
        for (int m = 0; m < NREG; m++) {
            float sim = G[n][m] * rn * s_rnorm[m];
            float aw  = an * s_area[m] * inv_aw;
            float cwv = co[n * NREG + m] * inv_cw;
            float v   = sim * aw * cwv;
            vals[m] = v;
            mx = fmaxf(mx, v);
        }
        float sum = 0.f;
        #pragma unroll
        for (int m = 0; m < NREG; m++) { vals[m] = expf(vals[m] - mx); sum += vals[m]; }
        float inv = 1.0f / sum;
        float* op = out + ((size_t)b * NREG * NREG + n * NREG);
        #pragma unroll
        for (int m = 0; m < NREG; m++) op[m] = vals[m] * inv;
    }
}

// ---------------------------------------------------------------------------
// kernel_launch
// Inputs (metadata order): region_features [8192,14,768] f32, area_matrix
// [8192,14] f32, co_occurrence_count [14,14] f32, W [768,768] f32, b [768] f32.
// Output: [8192,14,14] f32.
// ---------------------------------------------------------------------------
extern "C" void kernel_launch(void* const* d_in, const int* in_sizes, int n_in,
                              void* d_out, int out_size) {
    const float* X    = (const float*)d_in[0];
    const float* area = (const float*)d_in[1];
    const float* co   = (const float*)d_in[2];
    const float* W    = (const float*)d_in[3];
    const float* bias = (const float*)d_in[4];
    float* out        = (float*)d_out;

    cvtA_kernel<<<(M_TOTAL * (size_t)K_DIM) / 2048, 256>>>(X);   // 43008 blocks
    cvtW_kernel<<<((size_t)K_DIM * N_DIM) / 2048, 256>>>(W);     // 288 blocks
    gemm_kernel<<<dim3(N_DIM / 128, M_TOTAL / 128), 256>>>(bias);
    batch_kernel<<<BATCH, 448>>>(area, co, out);
}

// round 10
// speedup vs baseline: 1.2676x; 1.2676x over previous
#include <cuda_runtime.h>
#include <cuda_bf16.h>
#include <cstdint>
#include <cstddef>

// Problem dims (fixed by the dataset)
#define BATCH   8192
#define NREG    14
#define DDIM    768
#define M_TOTAL (BATCH * NREG)   // 114688 = 128 * 896
#define K_DIM   768              // 32 * 24
#define N_DIM   768              // 128 * 6

// ---------------------------------------------------------------------------
// Device scratch (allocation-free rule: __device__ globals)
// ---------------------------------------------------------------------------
__device__ __nv_bfloat16 g_Abf[(size_t)M_TOTAL * K_DIM];   // X in bf16
__device__ __nv_bfloat16 g_Wbf[(size_t)K_DIM * N_DIM];     // W in bf16
__device__ __nv_bfloat16 g_feats[(size_t)M_TOTAL * N_DIM]; // X@W + b in bf16

// ---------------------------------------------------------------------------
// fp32 -> bf16 converters (8 elems / thread, fully vectorized)
// ---------------------------------------------------------------------------
__global__ __launch_bounds__(256) void cvtA_kernel(const float* __restrict__ src) {
    size_t i = ((size_t)blockIdx.x * 256 + threadIdx.x) * 8;
    float4 v0 = *(const float4*)(src + i);
    float4 v1 = *(const float4*)(src + i + 4);
    union { __nv_bfloat162 h[4]; uint4 u; } pk;
    pk.h[0] = __floats2bfloat162_rn(v0.x, v0.y);
    pk.h[1] = __floats2bfloat162_rn(v0.z, v0.w);
    pk.h[2] = __floats2bfloat162_rn(v1.x, v1.y);
    pk.h[3] = __floats2bfloat162_rn(v1.z, v1.w);
    *(uint4*)(g_Abf + i) = pk.u;
}

__global__ __launch_bounds__(256) void cvtW_kernel(const float* __restrict__ src) {
    size_t i = ((size_t)blockIdx.x * 256 + threadIdx.x) * 8;
    float4 v0 = *(const float4*)(src + i);
    float4 v1 = *(const float4*)(src + i + 4);
    union { __nv_bfloat162 h[4]; uint4 u; } pk;
    pk.h[0] = __floats2bfloat162_rn(v0.x, v0.y);
    pk.h[1] = __floats2bfloat162_rn(v0.z, v0.w);
    pk.h[2] = __floats2bfloat162_rn(v1.x, v1.y);
    pk.h[3] = __floats2bfloat162_rn(v1.z, v1.w);
    *(uint4*)(g_Wbf + i) = pk.u;
}

// ---------------------------------------------------------------------------
// Shared PTX wrappers
// ---------------------------------------------------------------------------
__device__ __forceinline__ void cp_async16(uint32_t smem, const void* g) {
    asm volatile("cp.async.cg.shared.global [%0], [%1], 16;\n" :: "r"(smem), "l"(g));
}
__device__ __forceinline__ void ldm_x4(uint32_t& r0, uint32_t& r1, uint32_t& r2, uint32_t& r3,
                                       uint32_t addr) {
    asm volatile("ldmatrix.sync.aligned.m8n8.x4.shared.b16 {%0,%1,%2,%3}, [%4];"
                 : "=r"(r0), "=r"(r1), "=r"(r2), "=r"(r3) : "r"(addr));
}
__device__ __forceinline__ void ldm_x2(uint32_t& r0, uint32_t& r1, uint32_t addr) {
    asm volatile("ldmatrix.sync.aligned.m8n8.x2.shared.b16 {%0,%1}, [%2];"
                 : "=r"(r0), "=r"(r1) : "r"(addr));
}
__device__ __forceinline__ void ldm_x4_t(uint32_t& r0, uint32_t& r1, uint32_t& r2, uint32_t& r3,
                                         uint32_t addr) {
    asm volatile("ldmatrix.sync.aligned.m8n8.x4.trans.shared.b16 {%0,%1,%2,%3}, [%4];"
                 : "=r"(r0), "=r"(r1), "=r"(r2), "=r"(r3) : "r"(addr));
}
__device__ __forceinline__ void mma_bf16(float* d, const uint32_t* a, uint32_t b0, uint32_t b1) {
    asm volatile("mma.sync.aligned.m16n8k16.row.col.f32.bf16.bf16.f32 "
                 "{%0,%1,%2,%3}, {%4,%5,%6,%7}, {%8,%9}, {%0,%1,%2,%3};"
                 : "+f"(d[0]), "+f"(d[1]), "+f"(d[2]), "+f"(d[3])
                 : "r"(a[0]), "r"(a[1]), "r"(a[2]), "r"(a[3]), "r"(b0), "r"(b1));
}

// ---------------------------------------------------------------------------
// bf16 tensor-core GEMM: feats[M,768] = Abf[M,768] @ Wbf[768,768] + bias
// BM=128, BN=128, BK=32, 256 threads (8 warps, warp tile 32x64), 3-stage
// cp.async pipeline (48 KB static smem = ptxas limit), xor-swizzled smem.
// ---------------------------------------------------------------------------
#define KTILES 24
#define STAGES 3

__global__ __launch_bounds__(256, 2) void gemm_kernel(const float* __restrict__ bias) {
    __shared__ __nv_bfloat16 sA[STAGES][128 * 32];   // 24 KB
    __shared__ __nv_bfloat16 sB[STAGES][32 * 128];   // 24 KB  (total 48 KB = static max)

    const int tid  = threadIdx.x;
    const int lane = tid & 31;
    const int wid  = tid >> 5;
    const int wm   = (wid & 3) * 32;   // warp row offset within 128
    const int wn   = (wid >> 2) * 64;  // warp col offset within 128
    const int bn0  = blockIdx.x * 128;
    const size_t Abase = (size_t)blockIdx.y * 128 * K_DIM;

    const uint32_t sA_u = (uint32_t)__cvta_generic_to_shared(&sA[0][0]);
    const uint32_t sB_u = (uint32_t)__cvta_generic_to_shared(&sB[0][0]);

    auto loadTiles = [&](int stage, int kt) {
        // A tile: 128 rows x 4 chunks(16B). swizzle: chunk ^= (row>>1)&3
        #pragma unroll
        for (int j = 0; j < 2; j++) {
            int id = tid + j * 256;
            int r  = id >> 2, c = id & 3;
            const __nv_bfloat16* src = g_Abf + Abase + (size_t)r * K_DIM + kt * 32 + c * 8;
            int swc = c ^ ((r >> 1) & 3);
            cp_async16(sA_u + (uint32_t)((stage * 4096 + r * 32 + swc * 8) * 2), src);
        }
        // B tile: 32 rows x 16 chunks(16B). swizzle: chunk ^= row&7
        #pragma unroll
        for (int j = 0; j < 2; j++) {
            int id = tid + j * 256;
            int k  = id >> 4, c = id & 15;
            const __nv_bfloat16* src = g_Wbf + (size_t)(kt * 32 + k) * N_DIM + bn0 + c * 8;
            int swc = c ^ (k & 7);
            cp_async16(sB_u + (uint32_t)((stage * 4096 + k * 128 + swc * 8) * 2), src);
        }
        asm volatile("cp.async.commit_group;\n");
    };

    float acc[2][8][4];
    #pragma unroll
    for (int mf = 0; mf < 2; mf++)
        #pragma unroll
        for (int nf = 0; nf < 8; nf++)
            #pragma unroll
            for (int i = 0; i < 4; i++) acc[mf][nf][i] = 0.f;

    loadTiles(0, 0);
    loadTiles(1, 1);

    int cur = 0, nxt = 2;
    for (int kt = 0; kt < KTILES; kt++) {
        if (kt < KTILES - 1) asm volatile("cp.async.wait_group 1;\n");
        else                 asm volatile("cp.async.wait_group 0;\n");
        __syncthreads();
        if (kt + 2 < KTILES) loadTiles(nxt, kt + 2);

        #pragma unroll
        for (int kk = 0; kk < 2; kk++) {
            uint32_t afr[2][4], bfr[16];
            #pragma unroll
            for (int mf = 0; mf < 2; mf++) {
                int r   = wm + mf * 16 + (lane & 15);
                int ch  = kk * 2 + (lane >> 4);
                int swc = ch ^ ((r >> 1) & 3);
                ldm_x4(afr[mf][0], afr[mf][1], afr[mf][2], afr[mf][3],
                       sA_u + (uint32_t)((cur * 4096 + r * 32 + swc * 8) * 2));
            }
            #pragma unroll
            for (int nq = 0; nq < 4; nq++) {
                int k   = kk * 16 + (lane & 15);
                int ch  = (wn >> 3) + nq * 2 + (lane >> 4);
                int swc = ch ^ (k & 7);
                ldm_x4_t(bfr[nq * 4 + 0], bfr[nq * 4 + 1], bfr[nq * 4 + 2], bfr[nq * 4 + 3],
                         sB_u + (uint32_t)((cur * 4096 + k * 128 + swc * 8) * 2));
            }
            #pragma unroll
            for (int mf = 0; mf < 2; mf++)
                #pragma unroll
                for (int nf = 0; nf < 8; nf++)
                    mma_bf16(acc[mf][nf], afr[mf], bfr[2 * nf], bfr[2 * nf + 1]);
        }
        cur = cur == 2 ? 0 : cur + 1;
        nxt = nxt == 2 ? 0 : nxt + 1;
    }

    // Epilogue: add bias (L1/L2-cached float2 loads), convert to bf16, store feats
    const int g = lane >> 2, t4 = lane & 3;
    #pragma unroll
    for (int mf = 0; mf < 2; mf++) {
        size_t row0 = (size_t)blockIdx.y * 128 + wm + mf * 16 + g;
        #pragma unroll
        for (int nf = 0; nf < 8; nf++) {
            int col   = wn + nf * 8 + t4 * 2;
            float2 bb = __ldg((const float2*)(bias + bn0 + col));
            __nv_bfloat162 v0 = __floats2bfloat162_rn(acc[mf][nf][0] + bb.x, acc[mf][nf][1] + bb.y);
            __nv_bfloat162 v1 = __floats2bfloat162_rn(acc[mf][nf][2] + bb.x, acc[mf][nf][3] + bb.y);
            *(__nv_bfloat162*)(g_feats + row0 * N_DIM + bn0 + col)       = v0;
            *(__nv_bfloat162*)(g_feats + (row0 + 8) * N_DIM + bn0 + col) = v1;
        }
    }
}

// ---------------------------------------------------------------------------
// Per-batch kernel v3: Gram (16x16 padded) via tensor-core mma over bf16 smem.
// 128 threads (4 warps); each warp accumulates a 192-wide K slice, partials
// reduced through smem. Pitch 776 bf16 => ldmatrix conflict-free (row r
// starts at bank 4r mod 32). Then norms, weighting, softmax.
// ---------------------------------------------------------------------------
#define FS_PITCH 776   // bf16 elements per row (768 + 8 pad)

__global__ __launch_bounds__(128) void batch_kernel(const float* __restrict__ area,
                                                    const float* __restrict__ co,
                                                    float* __restrict__ out) {
    __shared__ __nv_bfloat16 Fs[16 * FS_PITCH];  // 24832 B (rows 14,15 zeroed)
    __shared__ float Gp[4 * 256];                // per-warp 16x16 partials
    __shared__ float Gs[256];                    // reduced Gram, 16x16
    __shared__ float s_area[14];
    __shared__ float s_rnorm[14];
    __shared__ float s_scal[2];  // [0] = 1/(cwsum+eps), [1] = 1/(amax^2+eps)

    const int b = blockIdx.x, tid = threadIdx.x;
    const int wid = tid >> 5, lane = tid & 31;

    // Stage feats: raw bf16 copy (16B per uint4)
    const uint4* fb = (const uint4*)(g_feats + (size_t)b * NREG * DDIM);
    for (int idx = tid; idx < NREG * 96; idx += 128) {
        int n = idx / 96, c = idx - n * 96;            // c in 16B units
        *(uint4*)(Fs + n * FS_PITCH + c * 8) = fb[idx];
    }
    // Zero pad rows 14-15 (2 rows * 776 bf16 = 776 uint32)
    {
        uint32_t* z = (uint32_t*)(Fs + 14 * FS_PITCH);
        for (int i = tid; i < FS_PITCH; i += 128) z[i] = 0u;
    }
    if (tid < NREG) s_area[tid] = area[b * NREG + tid];
    if (tid == 14) {  // deterministic cw sum (exact fp32 serial)
        float s = 0.f;
        for (int i = 0; i < NREG * NREG; i++) s += co[i];
        s_scal[0] = 1.0f / (s + 1e-8f);
    }
    if (tid == 15) {  // max(aw) == (max a)^2 since a >= 0
        float am = 0.f;
        for (int i = 0; i < NREG; i++) am = fmaxf(am, area[b * NREG + i]);
        s_scal[1] = 1.0f / (am * am + 1e-8f);
    }
    __syncthreads();

    // Tensor-core Gram: warp `wid` handles K slice [wid*192, wid*192+192).
    {
        const uint32_t fs_u = (uint32_t)__cvta_generic_to_shared(Fs);
        float acc[2][4] = {{0.f, 0.f, 0.f, 0.f}, {0.f, 0.f, 0.f, 0.f}};
        const int kw = wid * 192;
        const int arow = lane & 15;                 // A rows 0..15
        const int aofs = (lane >> 4) << 3;          // +0 / +8 in k per half-warp
        const int brow = lane & 7;                  // B rows 0..7 within tile
        const int bofs = ((lane >> 3) & 1) << 3;    // +0 / +8 in k

        #pragma unroll
        for (int ks = 0; ks < 12; ks++) {
            const int kb = kw + ks * 16;
            uint32_t a[4], b0, b1, c0, c1;
            ldm_x4(a[0], a[1], a[2], a[3],
                   fs_u + (uint32_t)((arow * FS_PITCH + kb + aofs) << 1));
            ldm_x2(b0, b1,
                   fs_u + (uint32_t)((brow * FS_PITCH + kb + bofs) << 1));
            ldm_x2(c0, c1,
                   fs_u + (uint32_t)(((8 + brow) * FS_PITCH + kb + bofs) << 1));
            mma_bf16(acc[0], a, b0, b1);  // G rows 0-15, cols 0-7
            mma_bf16(acc[1], a, c0, c1);  // G rows 0-15, cols 8-15
        }

        // Write 16x16 partial (C fragment layout: c0,c1 row g8; c2,c3 row g8+8)
        float* gp = Gp + wid * 256;
        const int g8 = lane >> 2, q = (lane & 3) * 2;
        #pragma unroll
        for (int n = 0; n < 2; n++) {
            gp[g8 * 16 + n * 8 + q + 0]       = acc[n][0];
            gp[g8 * 16 + n * 8 + q + 1]       = acc[n][1];
            gp[(g8 + 8) * 16 + n * 8 + q + 0] = acc[n][2];
            gp[(g8 + 8) * 16 + n * 8 + q + 1] = acc[n][3];
        }
    }
    __syncthreads();

    // Reduce 4 partials (each thread: 2 elements)
    #pragma unroll
    for (int e = tid; e < 256; e += 128)
        Gs[e] = Gp[e] + Gp[256 + e] + Gp[512 + e] + Gp[768 + e];
    __syncthreads();

    if (tid < NREG)
        s_rnorm[tid] = 1.0f / fmaxf(sqrtf(Gs[tid * 17]), 1e-12f);
    __syncthreads();

    if (tid < NREG) {
        const int n = tid;
        float vals[NREG];
        const float an = s_area[n], rn = s_rnorm[n];
        const float inv_cw = s_scal[0], inv_aw = s_scal[1];
        float mx = -1e30f;
        #pragma unroll
        for (int m = 0; m < NREG; m++) {
            float sim = Gs[n * 16 + m] * rn * s_rnorm[m];
            float aw  = an * s_area[m] * inv_aw;
            float cwv = co[n * NREG + m] * inv_cw;
            float v   = sim * aw * cwv;
            vals[m] = v;
            mx = fmaxf(mx, v);
        }
        float sum = 0.f;
        #pragma unroll
        for (int m = 0; m < NREG; m++) { vals[m] = expf(vals[m] - mx); sum += vals[m]; }
        float inv = 1.0f / sum;
        float* op = out + ((size_t)b * NREG * NREG + n * NREG);
        #pragma unroll
        for (int m = 0; m < NREG; m++) op[m] = vals[m] * inv;
    }
}

// ---------------------------------------------------------------------------
// kernel_launch
// Inputs (metadata order): region_features [8192,14,768] f32, area_matrix
// [8192,14] f32, co_occurrence_count [14,14] f32, W [768,768] f32, b [768] f32.
// Output: [8192,14,14] f32.
// ---------------------------------------------------------------------------
extern "C" void kernel_launch(void* const* d_in, const int* in_sizes, int n_in,
                              void* d_out, int out_size) {
    const float* X    = (const float*)d_in[0];
    const float* area = (const float*)d_in[1];
    const float* co   = (const float*)d_in[2];
    const float* W    = (const float*)d_in[3];
    const float* bias = (const float*)d_in[4];
    float* out        = (float*)d_out;

    cvtA_kernel<<<(M_TOTAL * (size_t)K_DIM) / 2048, 256>>>(X);   // 43008 blocks
    cvtW_kernel<<<((size_t)K_DIM * N_DIM) / 2048, 256>>>(W);     // 288 blocks
    gemm_kernel<<<dim3(N_DIM / 128, M_TOTAL / 128), 256>>>(bias);
    batch_kernel<<<BATCH, 128>>>(area, co, out);
}